// round 1
// baseline (speedup 1.0000x reference)
#include <cuda_runtime.h>

// Problem constants (fixed by the dataset)
#define GSIDE 64
#define GRID3 (GSIDE * GSIDE * GSIDE)
#define NMAX  60000
#define CCH   64

// Scratch (static __device__ arrays — no allocations allowed)
__device__ float g_y[(size_t)NMAX * 8 * CCH];   // after up-conv + relu
__device__ float g_z[(size_t)NMAX * 8 * CCH];   // after conv1 + relu
__device__ int   g_grid[GRID3];                 // voxel -> input row, or -1

// ---------------------------------------------------------------------------
// occupancy grid build
// ---------------------------------------------------------------------------
__global__ void k_grid_init() {
    int i = blockIdx.x * 256 + threadIdx.x;
    if (i < GRID3) g_grid[i] = -1;
}

__global__ void k_scatter(const int* __restrict__ coords, int n) {
    int i = blockIdx.x * 256 + threadIdx.x;
    if (i < n) {
        int x = coords[i * 3 + 0];
        int y = coords[i * 3 + 1];
        int z = coords[i * 3 + 2];
        g_grid[x * (GSIDE * GSIDE) + y * GSIDE + z] = i;
    }
}

// ---------------------------------------------------------------------------
// up-conv: y[n*8+k] = relu(feats[n] @ W_up[k] + b_up)
// block = 256 threads, 8 input rows per block
// ---------------------------------------------------------------------------
__global__ __launch_bounds__(256) void k_up(const float* __restrict__ feats,
                                            const float* __restrict__ Wup,
                                            const float* __restrict__ bup,
                                            int n) {
    __shared__ float sF[8 * CCH];
    __shared__ float sW[CCH * CCH];
    const int tid = threadIdx.x;
    const int base = blockIdx.x * 8;

    #pragma unroll
    for (int i = 0; i < 2; i++) {
        int idx = tid + i * 256;
        int r = idx >> 6;
        sF[idx] = (base + r < n) ? feats[(size_t)base * CCH + idx] : 0.f;
    }

    for (int k = 0; k < 8; k++) {
        __syncthreads();  // sF ready (k=0) / previous compute done before sW overwrite
        const float4* Ws = (const float4*)(Wup + (size_t)k * CCH * CCH);
        float4* Wd = (float4*)sW;
        #pragma unroll
        for (int i = 0; i < 4; i++) Wd[tid + i * 256] = Ws[tid + i * 256];
        __syncthreads();

        #pragma unroll
        for (int h = 0; h < 2; h++) {
            int o = tid + h * 256;           // 512 outputs: 8 rows x 64 ch
            int r = o >> 6, d = o & 63;
            float a = bup[d];
            #pragma unroll 16
            for (int c = 0; c < CCH; c++) a = fmaf(sF[r * CCH + c], sW[c * CCH + d], a);
            if (base + r < n) {
                size_t row = (size_t)(base + r) * 8 + k;
                g_y[row * CCH + d] = fmaxf(a, 0.f);
            }
        }
    }
}

// ---------------------------------------------------------------------------
// sparse conv (27 taps, stride 1 on the child grid)
// block = 256 threads, tile = 8 parents = 64 output rows x 64 channels
// phase 0: X = g_y, out = g_z (relu); phase 1: X = g_z, out = out_ext
// ---------------------------------------------------------------------------
__global__ __launch_bounds__(256) void k_conv(int phase,
                                              const float* __restrict__ W,
                                              const float* __restrict__ bias,
                                              const int* __restrict__ coords,
                                              float* __restrict__ out_ext,
                                              int do_relu, int n) {
    __shared__ float sA[64 * 68];     // gathered neighbor tile (pitch 68 floats)
    __shared__ float sW[64 * 64];     // W[ko]
    __shared__ int   sN[64];          // neighbor row per output row (-1 = absent)

    const float* X = (phase == 0) ? g_y : g_z;
    float* out = (phase == 0) ? g_z : out_ext;

    const int tid = threadIdx.x;
    const int p0 = blockIdx.x * 8;
    const int ty = tid >> 4;          // 0..15 (row group of 4)
    const int tx = tid & 15;          // 0..15 (col group of 4)

    // per-row static info (rows handled by tid < 64)
    int pcx = 1000, pcy = 1000, pcz = 1000;   // dead value -> all lookups miss
    int chx = 0, chy = 0, chz = 0;
    if (tid < 64) {
        int p = p0 + (tid >> 3);
        if (p < n) {
            pcx = coords[p * 3 + 0];
            pcy = coords[p * 3 + 1];
            pcz = coords[p * 3 + 2];
        }
        int ch = tid & 7;
        chx = (ch >> 2) & 1;
        chy = (ch >> 1) & 1;
        chz = ch & 1;
    }

    float acc[16];
    #pragma unroll
    for (int i = 0; i < 16; i++) acc[i] = 0.f;

    for (int ko = 0; ko < 27; ko++) {
        const int ox = ko / 9 - 1;
        const int oy = (ko / 3) % 3 - 1;
        const int oz = ko % 3 - 1;

        int nbr = -1;
        if (tid < 64) {
            int qx = 2 * pcx + chx + ox;
            int qy = 2 * pcy + chy + oy;
            int qz = 2 * pcz + chz + oz;
            int px = qx >> 1, py = qy >> 1, pz = qz >> 1;  // floor div (arith shift)
            if ((unsigned)px < 64u && (unsigned)py < 64u && (unsigned)pz < 64u) {
                int g = g_grid[px * 4096 + py * 64 + pz];
                if (g >= 0)
                    nbr = g * 8 + ((qx & 1) << 2) + ((qy & 1) << 1) + (qz & 1);
            }
            sN[tid] = nbr;
        }
        int cnt = __syncthreads_count(nbr >= 0);
        if (cnt == 0) continue;       // whole tile has no neighbor for this tap

        // load W[ko] into smem (4096 floats, 1024 float4, 256 threads)
        {
            const float4* Ws = (const float4*)(W + (size_t)ko * 4096);
            float4* Wd = (float4*)sW;
            #pragma unroll
            for (int i = 0; i < 4; i++) Wd[tid + i * 256] = Ws[tid + i * 256];
        }
        // gather A tile: thread -> row tid>>2, 16 floats at col (tid&3)*16
        {
            int row = tid >> 2;
            int cg = (tid & 3) * 16;
            int nb = sN[row];
            float4 v0, v1, v2, v3;
            if (nb >= 0) {
                const float4* src = (const float4*)(X + (size_t)nb * CCH + cg);
                v0 = src[0]; v1 = src[1]; v2 = src[2]; v3 = src[3];
            } else {
                v0 = v1 = v2 = v3 = make_float4(0.f, 0.f, 0.f, 0.f);
            }
            float4* dst = (float4*)(sA + row * 68 + cg);
            dst[0] = v0; dst[1] = v1; dst[2] = v2; dst[3] = v3;
        }
        __syncthreads();

        // GEMM: acc[4x4] += A[64x64] @ W[64x64] tile
        #pragma unroll 4
        for (int c = 0; c < 64; c += 4) {
            float4 a0 = *(const float4*)&sA[(ty * 4 + 0) * 68 + c];
            float4 a1 = *(const float4*)&sA[(ty * 4 + 1) * 68 + c];
            float4 a2 = *(const float4*)&sA[(ty * 4 + 2) * 68 + c];
            float4 a3 = *(const float4*)&sA[(ty * 4 + 3) * 68 + c];
            const float av0[4] = {a0.x, a0.y, a0.z, a0.w};
            const float av1[4] = {a1.x, a1.y, a1.z, a1.w};
            const float av2[4] = {a2.x, a2.y, a2.z, a2.w};
            const float av3[4] = {a3.x, a3.y, a3.z, a3.w};
            #pragma unroll
            for (int j = 0; j < 4; j++) {
                float4 w = *(const float4*)&sW[(c + j) * 64 + tx * 4];
                acc[0]  = fmaf(av0[j], w.x, acc[0]);
                acc[1]  = fmaf(av0[j], w.y, acc[1]);
                acc[2]  = fmaf(av0[j], w.z, acc[2]);
                acc[3]  = fmaf(av0[j], w.w, acc[3]);
                acc[4]  = fmaf(av1[j], w.x, acc[4]);
                acc[5]  = fmaf(av1[j], w.y, acc[5]);
                acc[6]  = fmaf(av1[j], w.z, acc[6]);
                acc[7]  = fmaf(av1[j], w.w, acc[7]);
                acc[8]  = fmaf(av2[j], w.x, acc[8]);
                acc[9]  = fmaf(av2[j], w.y, acc[9]);
                acc[10] = fmaf(av2[j], w.z, acc[10]);
                acc[11] = fmaf(av2[j], w.w, acc[11]);
                acc[12] = fmaf(av3[j], w.x, acc[12]);
                acc[13] = fmaf(av3[j], w.y, acc[13]);
                acc[14] = fmaf(av3[j], w.z, acc[14]);
                acc[15] = fmaf(av3[j], w.w, acc[15]);
            }
        }
        __syncthreads();
    }

    // epilogue: bias (+ optional relu), write 4x4 per thread
    float4 bb = *(const float4*)(bias + tx * 4);
    #pragma unroll
    for (int i = 0; i < 4; i++) {
        int m = ty * 4 + i;
        int p = p0 + (m >> 3);
        if (p >= n) continue;
        float4 r;
        r.x = acc[i * 4 + 0] + bb.x;
        r.y = acc[i * 4 + 1] + bb.y;
        r.z = acc[i * 4 + 2] + bb.z;
        r.w = acc[i * 4 + 3] + bb.w;
        if (do_relu) {
            r.x = fmaxf(r.x, 0.f);
            r.y = fmaxf(r.y, 0.f);
            r.z = fmaxf(r.z, 0.f);
            r.w = fmaxf(r.w, 0.f);
        }
        size_t row = (size_t)p0 * 8 + m;
        *(float4*)(out + row * CCH + tx * 4) = r;
    }
}

// ---------------------------------------------------------------------------
extern "C" void kernel_launch(void* const* d_in, const int* in_sizes, int n_in,
                              void* d_out, int out_size) {
    const int*   coords = (const int*)d_in[0];
    const float* feats  = (const float*)d_in[1];
    const float* W_up   = (const float*)d_in[2];
    const float* b_up   = (const float*)d_in[3];
    const float* W1     = (const float*)d_in[4];
    const float* b1     = (const float*)d_in[5];
    const float* W2     = (const float*)d_in[6];
    const float* b2     = (const float*)d_in[7];
    float* out = (float*)d_out;

    int n = in_sizes[0] / 3;   // number of occupied input voxels

    k_grid_init<<<(GRID3 + 255) / 256, 256>>>();
    k_scatter<<<(n + 255) / 256, 256>>>(coords, n);

    int nb = (n + 7) / 8;
    k_up<<<nb, 256>>>(feats, W_up, b_up, n);
    k_conv<<<nb, 256>>>(0, W1, b1, coords, out, 1, n);
    k_conv<<<nb, 256>>>(1, W2, b2, coords, out, 0, n);
}

// round 2
// speedup vs baseline: 1.1305x; 1.1305x over previous
#include <cuda_runtime.h>

// Problem constants (fixed by the dataset)
#define GSIDE 64
#define GRID3 (GSIDE * GSIDE * GSIDE)
#define NMAX  60000
#define CCH   64

// Scratch (static __device__ arrays — no allocations allowed)
__device__ float g_y[(size_t)NMAX * 8 * CCH];   // after up-conv + relu
__device__ float g_z[(size_t)NMAX * 8 * CCH];   // after conv1 + relu
__device__ int   g_grid[GRID3];                 // voxel -> input row, or -1

// ---------------------------------------------------------------------------
// occupancy grid build
// ---------------------------------------------------------------------------
__global__ void k_grid_init() {
    int i = blockIdx.x * 256 + threadIdx.x;
    if (i < GRID3) g_grid[i] = -1;
}

__global__ void k_scatter(const int* __restrict__ coords, int n) {
    int i = blockIdx.x * 256 + threadIdx.x;
    if (i < n) {
        int x = coords[i * 3 + 0];
        int y = coords[i * 3 + 1];
        int z = coords[i * 3 + 2];
        g_grid[x * (GSIDE * GSIDE) + y * GSIDE + z] = i;
    }
}

// ---------------------------------------------------------------------------
// up-conv: y[n*8+k] = relu(feats[n] @ W_up[k] + b_up)
// block = 256 threads, 8 input rows per block
// ---------------------------------------------------------------------------
__global__ __launch_bounds__(256) void k_up(const float* __restrict__ feats,
                                            const float* __restrict__ Wup,
                                            const float* __restrict__ bup,
                                            int n) {
    __shared__ float sF[8 * CCH];
    __shared__ float sW[CCH * CCH];
    const int tid = threadIdx.x;
    const int base = blockIdx.x * 8;

    #pragma unroll
    for (int i = 0; i < 2; i++) {
        int idx = tid + i * 256;
        int r = idx >> 6;
        sF[idx] = (base + r < n) ? feats[(size_t)base * CCH + idx] : 0.f;
    }

    for (int k = 0; k < 8; k++) {
        __syncthreads();
        const float4* Ws = (const float4*)(Wup + (size_t)k * CCH * CCH);
        float4* Wd = (float4*)sW;
        #pragma unroll
        for (int i = 0; i < 4; i++) Wd[tid + i * 256] = Ws[tid + i * 256];
        __syncthreads();

        #pragma unroll
        for (int h = 0; h < 2; h++) {
            int o = tid + h * 256;           // 512 outputs: 8 rows x 64 ch
            int r = o >> 6, d = o & 63;
            float a = bup[d];
            #pragma unroll 16
            for (int c = 0; c < CCH; c++) a = fmaf(sF[r * CCH + c], sW[c * CCH + d], a);
            if (base + r < n) {
                size_t row = (size_t)(base + r) * 8 + k;
                g_y[row * CCH + d] = fmaxf(a, 0.f);
            }
        }
    }
}

// ---------------------------------------------------------------------------
// sparse conv (27 taps, stride 1 on the child grid)
// tile = 16 parents = 128 output rows x 64 channels, 128 threads, 8x8/thread
// A tile stored K-major in smem so per-k reads are 2x LDS.128 per operand.
// ---------------------------------------------------------------------------
#define TM 128
__global__ __launch_bounds__(128, 4) void k_conv(int phase,
                                                 const float* __restrict__ W,
                                                 const float* __restrict__ bias,
                                                 const int* __restrict__ coords,
                                                 float* __restrict__ out_ext,
                                                 int do_relu, int n) {
    __shared__ float sAT[64 * TM];    // [c][m] K-major gathered tile, 32 KB
    __shared__ float sW[64 * 64];     // W[ko], 16 KB

    const float* X = (phase == 0) ? g_y : g_z;
    float* out = (phase == 0) ? g_z : out_ext;

    const int tid = threadIdx.x;
    const int p0 = blockIdx.x * 16;           // 16 parents per tile
    const int ty = tid >> 3;                  // 0..15 -> rows ty*8..ty*8+7
    const int tx = tid & 7;                   // 0..7  -> cols tx*8..tx*8+7

    // this thread's own output row (and gather row) = tid
    const int m = tid;
    const int pi = p0 + (m >> 3);
    int pcx = 1000, pcy = 1000, pcz = 1000;   // dead value -> all lookups miss
    if (pi < n) {
        pcx = coords[pi * 3 + 0];
        pcy = coords[pi * 3 + 1];
        pcz = coords[pi * 3 + 2];
    }
    const int ch = m & 7;
    const int chx = (ch >> 2) & 1;
    const int chy = (ch >> 1) & 1;
    const int chz = ch & 1;

    float acc[8][8];
    #pragma unroll
    for (int i = 0; i < 8; i++)
        #pragma unroll
        for (int j = 0; j < 8; j++) acc[i][j] = 0.f;

    for (int ko = 0; ko < 27; ko++) {
        const int ox = ko / 9 - 1;
        const int oy = (ko / 3) % 3 - 1;
        const int oz = ko % 3 - 1;

        // neighbor lookup for this thread's row
        int nbr = -1;
        {
            int qx = 2 * pcx + chx + ox;
            int qy = 2 * pcy + chy + oy;
            int qz = 2 * pcz + chz + oz;
            int px = qx >> 1, py = qy >> 1, pz = qz >> 1;   // floor div
            if ((unsigned)px < 64u && (unsigned)py < 64u && (unsigned)pz < 64u) {
                int g = g_grid[px * 4096 + py * 64 + pz];
                if (g >= 0)
                    nbr = g * 8 + ((qx & 1) << 2) + ((qy & 1) << 1) + (qz & 1);
            }
        }
        // barrier (also guards sAT/sW overwrite vs previous GEMM) + tile skip
        int cnt = __syncthreads_count(nbr >= 0);
        if (cnt == 0) continue;

        // load W[ko] into smem: 4096 floats = 1024 float4, 128 threads x 8
        {
            const float4* Ws = (const float4*)(W + (size_t)ko * 4096);
            float4* Wd = (float4*)sW;
            #pragma unroll
            for (int i = 0; i < 8; i++) Wd[tid + i * 128] = Ws[tid + i * 128];
        }
        // gather this thread's row, transposed into sAT[c][m]
        if (nbr >= 0) {
            const float4* src = (const float4*)(X + (size_t)nbr * CCH);
            #pragma unroll
            for (int c4 = 0; c4 < 16; c4++) {
                float4 v = src[c4];
                int c = c4 * 4;
                sAT[(c + 0) * TM + m] = v.x;
                sAT[(c + 1) * TM + m] = v.y;
                sAT[(c + 2) * TM + m] = v.z;
                sAT[(c + 3) * TM + m] = v.w;
            }
        } else {
            #pragma unroll
            for (int c = 0; c < 64; c++) sAT[c * TM + m] = 0.f;
        }
        __syncthreads();

        // GEMM: acc[8x8] += A[128x64] @ W[64x64] tile
        #pragma unroll 8
        for (int c = 0; c < 64; c++) {
            float4 a0 = *(const float4*)&sAT[c * TM + ty * 8];
            float4 a1 = *(const float4*)&sAT[c * TM + ty * 8 + 4];
            float4 w0 = *(const float4*)&sW[c * 64 + tx * 8];
            float4 w1 = *(const float4*)&sW[c * 64 + tx * 8 + 4];
            const float av[8] = {a0.x, a0.y, a0.z, a0.w, a1.x, a1.y, a1.z, a1.w};
            const float wv[8] = {w0.x, w0.y, w0.z, w0.w, w1.x, w1.y, w1.z, w1.w};
            #pragma unroll
            for (int i = 0; i < 8; i++)
                #pragma unroll
                for (int j = 0; j < 8; j++)
                    acc[i][j] = fmaf(av[i], wv[j], acc[i][j]);
        }
    }

    // epilogue: bias (+ optional relu), write 8x8 per thread
    float4 b0 = *(const float4*)(bias + tx * 8);
    float4 b1 = *(const float4*)(bias + tx * 8 + 4);
    const float bv[8] = {b0.x, b0.y, b0.z, b0.w, b1.x, b1.y, b1.z, b1.w};
    #pragma unroll
    for (int i = 0; i < 8; i++) {
        int mr = ty * 8 + i;
        int p = p0 + (mr >> 3);
        if (p >= n) continue;
        float r[8];
        #pragma unroll
        for (int j = 0; j < 8; j++) {
            r[j] = acc[i][j] + bv[j];
            if (do_relu) r[j] = fmaxf(r[j], 0.f);
        }
        size_t row = (size_t)p0 * 8 + mr;
        float* dst = out + row * CCH + tx * 8;
        *(float4*)dst = make_float4(r[0], r[1], r[2], r[3]);
        *(float4*)(dst + 4) = make_float4(r[4], r[5], r[6], r[7]);
    }
}

// ---------------------------------------------------------------------------
extern "C" void kernel_launch(void* const* d_in, const int* in_sizes, int n_in,
                              void* d_out, int out_size) {
    const int*   coords = (const int*)d_in[0];
    const float* feats  = (const float*)d_in[1];
    const float* W_up   = (const float*)d_in[2];
    const float* b_up   = (const float*)d_in[3];
    const float* W1     = (const float*)d_in[4];
    const float* b1     = (const float*)d_in[5];
    const float* W2     = (const float*)d_in[6];
    const float* b2     = (const float*)d_in[7];
    float* out = (float*)d_out;

    int n = in_sizes[0] / 3;   // number of occupied input voxels

    k_grid_init<<<(GRID3 + 255) / 256, 256>>>();
    k_scatter<<<(n + 255) / 256, 256>>>(coords, n);

    k_up<<<(n + 7) / 8, 256>>>(feats, W_up, b_up, n);

    int nb = (n + 15) / 16;
    k_conv<<<nb, 128>>>(0, W1, b1, coords, out, 1, n);
    k_conv<<<nb, 128>>>(1, W2, b2, coords, out, 0, n);
}